// round 15
// baseline (speedup 1.0000x reference)
#include <cuda_runtime.h>
#include <cuda_bf16.h>
#include <stdint.h>

#define BB 8
#define NN 4096
#define CC 64
#define QD 8
#define BM 64          // query rows per block
#define BN 64          // key tile rows
#define QT (NN / BM)
#define KT (NN / BN)
#define LDH 72         // sH leading dim
#define LDO 72         // epilogue O overlay leading dim (floats)
#define LOG2E 1.4426950408889634f

// Static device scratch for projections.
__device__ __nv_bfloat16 g_f[BB * NN * QD];   // 0.5 MB
__device__ __nv_bfloat16 g_g[BB * NN * QD];   // 0.5 MB (pre-scaled by log2e)
__device__ __nv_bfloat16 g_h[BB * NN * CC];   // 4 MB

// ---------------------------------------------------------------------------
// PTX helpers
// ---------------------------------------------------------------------------
__device__ __forceinline__ void mma_16n8k8(float* c, const uint32_t* a, uint32_t b)
{
    asm volatile(
        "mma.sync.aligned.m16n8k8.row.col.f32.bf16.bf16.f32 "
        "{%0,%1,%2,%3}, {%4,%5}, {%6}, {%0,%1,%2,%3};\n"
        : "+f"(c[0]), "+f"(c[1]), "+f"(c[2]), "+f"(c[3])
        : "r"(a[0]), "r"(a[1]), "r"(b));
}

__device__ __forceinline__ void mma_16n8k16(float* c, const uint32_t* a, const uint32_t* b)
{
    asm volatile(
        "mma.sync.aligned.m16n8k16.row.col.f32.bf16.bf16.f32 "
        "{%0,%1,%2,%3}, {%4,%5,%6,%7}, {%8,%9}, {%0,%1,%2,%3};\n"
        : "+f"(c[0]), "+f"(c[1]), "+f"(c[2]), "+f"(c[3])
        : "r"(a[0]), "r"(a[1]), "r"(a[2]), "r"(a[3]), "r"(b[0]), "r"(b[1]));
}

__device__ __forceinline__ void ldsm_x4(uint32_t* r, const void* smem_ptr)
{
    uint32_t addr = (uint32_t)__cvta_generic_to_shared(smem_ptr);
    asm volatile(
        "ldmatrix.sync.aligned.m8n8.x4.shared.b16 {%0,%1,%2,%3}, [%4];\n"
        : "=r"(r[0]), "=r"(r[1]), "=r"(r[2]), "=r"(r[3]) : "r"(addr));
}

__device__ __forceinline__ void ldsm_x4_trans(uint32_t* r, const void* smem_ptr)
{
    uint32_t addr = (uint32_t)__cvta_generic_to_shared(smem_ptr);
    asm volatile(
        "ldmatrix.sync.aligned.m8n8.x4.trans.shared.b16 {%0,%1,%2,%3}, [%4];\n"
        : "=r"(r[0]), "=r"(r[1]), "=r"(r[2]), "=r"(r[3]) : "r"(addr));
}

__device__ __forceinline__ uint32_t pack_bf162(float a, float b)
{
    __nv_bfloat162 t = __floats2bfloat162_rn(a, b);
    return *(uint32_t*)&t;
}

// cvt two fp32 -> bf16x2 (lo, hi), then exp2 both halves in ONE MUFU op.
__device__ __forceinline__ uint32_t ex2_pair(float lo, float hi)
{
    uint32_t t, y;
    asm("cvt.rn.bf16x2.f32 %0, %1, %2;\n" : "=r"(t) : "f"(hi), "f"(lo));
    asm("ex2.approx.ftz.bf16x2 %0, %1;\n" : "=r"(y) : "r"(t));
    return y;
}

__device__ __forceinline__ void cp_async16(void* smem_dst, const void* gmem_src)
{
    uint32_t d = (uint32_t)__cvta_generic_to_shared(smem_dst);
    asm volatile("cp.async.cg.shared.global [%0], [%1], 16;\n"
                 :: "r"(d), "l"(gmem_src) : "memory");
}
__device__ __forceinline__ void cp_async_commit()
{
    asm volatile("cp.async.commit_group;\n" ::: "memory");
}
__device__ __forceinline__ void cp_async_wait0()
{
    asm volatile("cp.async.wait_group 0;\n" ::: "memory");
}

// ---------------------------------------------------------------------------
// Kernel 1: projections as HMMA GEMM.  [64 rows x 64] @ [64 x 80] per block.
// 512 blocks x 128 threads (4 warps, 16 rows each), float4 weight staging.
// Wg pre-scaled by log2e.
// ---------------------------------------------------------------------------
#define LDW 88
#define LDX 72
__global__ __launch_bounds__(128) void proj_kernel(
    const float* __restrict__ x,
    const float* __restrict__ kf,
    const float* __restrict__ kg,
    const float* __restrict__ kh)
{
    __shared__ __nv_bfloat16 sW[64 * LDW];    // row c: d 0-7 f, 8-15 g(scaled), 16-79 h
    __shared__ __nv_bfloat16 sX[64 * LDX];

    int tid  = threadIdx.x;
    int lane = tid & 31;
    int w    = tid >> 5;
    int gid  = lane >> 2;
    int tg   = lane & 3;

    // Vectorized weight staging: flat float4 index over [kf | kg | kh].
    for (int i = tid; i < 1280; i += 128) {
        float4 v;
        int c, d;
        float sc = 1.f;
        if (i < 128) {
            v = ((const float4*)kf)[i];
            int e = i * 4;  c = e >> 3;  d = e & 7;
        } else if (i < 256) {
            v = ((const float4*)kg)[i - 128];
            int e = (i - 128) * 4;  c = e >> 3;  d = (e & 7) + 8;
            sc = LOG2E;
        } else {
            v = ((const float4*)kh)[i - 256];
            int e = (i - 256) * 4;  c = e >> 6;  d = (e & 63) + 16;
        }
        __nv_bfloat16* dst = &sW[c * LDW + d];
        dst[0] = __float2bfloat16(v.x * sc);
        dst[1] = __float2bfloat16(v.y * sc);
        dst[2] = __float2bfloat16(v.z * sc);
        dst[3] = __float2bfloat16(v.w * sc);
    }
    long base = (long)blockIdx.x * 64;
    const float4* xg = (const float4*)(x + base * 64);
    for (int i = tid; i < 1024; i += 128) {
        int r = i >> 4, c4 = (i & 15) * 4;
        float4 v = xg[i];
        __nv_bfloat162* dst = (__nv_bfloat162*)&sX[r * LDX + c4];
        dst[0] = __floats2bfloat162_rn(v.x, v.y);
        dst[1] = __floats2bfloat162_rn(v.z, v.w);
    }
    __syncthreads();

    float c[10][4];
#pragma unroll
    for (int n = 0; n < 10; n++)
#pragma unroll
        for (int i = 0; i < 4; i++) c[n][i] = 0.f;

#pragma unroll
    for (int kk = 0; kk < 4; kk++) {
        uint32_t a[4];
        ldsm_x4(a, &sX[(w * 16 + (lane & 15)) * LDX + kk * 16 + (lane >> 4) * 8]);
#pragma unroll
        for (int np = 0; np < 5; np++) {
            uint32_t bfr[4];
            ldsm_x4_trans(bfr,
                &sW[(kk * 16 + (lane & 15)) * LDW + np * 16 + (lane >> 4) * 8]);
            mma_16n8k16(c[2 * np],     a, &bfr[0]);
            mma_16n8k16(c[2 * np + 1], a, &bfr[2]);
        }
    }

    // Fragment-direct scattered stores: d = 16*np + 8*h + 2*tg (static routing).
    long r0 = base + w * 16 + gid;
    long r1 = r0 + 8;
#pragma unroll
    for (int np = 0; np < 5; np++) {
#pragma unroll
        for (int h = 0; h < 2; h++) {
            int dbase = 16 * np + 8 * h;
            uint32_t u0 = pack_bf162(c[2 * np + h][0], c[2 * np + h][1]);
            uint32_t u1 = pack_bf162(c[2 * np + h][2], c[2 * np + h][3]);
            if (dbase == 0) {
                *(uint32_t*)&g_f[r0 * QD + 2 * tg] = u0;
                *(uint32_t*)&g_f[r1 * QD + 2 * tg] = u1;
            } else if (dbase == 8) {
                *(uint32_t*)&g_g[r0 * QD + 2 * tg] = u0;
                *(uint32_t*)&g_g[r1 * QD + 2 * tg] = u1;
            } else {
                int d = dbase - 16 + 2 * tg;
                *(uint32_t*)&g_h[r0 * CC + d] = u0;
                *(uint32_t*)&g_h[r1 * CC + d] = u1;
            }
        }
    }
}

// ---------------------------------------------------------------------------
// Kernel 2: flash attention. 128 threads = 2 key-parity pairs (2 warps each).
// Pair p handles key tiles kt = p, p+2, ...; warp-in-pair wp covers rows
// [wp*32, wp*32+32) as two m16 chunks sharing every H B-fragment.
// S is software-pipelined one 16-key slab ahead ACROSS iteration boundaries
// (true modulo schedule): the next slab's F fragments are loaded per-slab
// (2 LDS.32) and its 4 S-MMAs issued before the current slab's ex2/PV, so
// S latency is never exposed. Row-sums on the tensor pipe (ones column).
// Symmetric epilogue: pair 0 finalizes rows 0-31, pair 1 rows 32-63.
// ---------------------------------------------------------------------------
__global__ __launch_bounds__(128, 3) void attn_kernel(
    const float* __restrict__ x,
    const float* __restrict__ gamma_p,
    float* __restrict__ out)
{
    __shared__ __nv_bfloat16 sG[BM * QD];             // 1 KB
    __shared__ __nv_bfloat16 sF[2][2][BN * QD];       // 4 KB   [pair][buf]
    __shared__ __nv_bfloat16 sH[2][2][BN * LDH];      // 36 KB  [pair][buf]
    __shared__ float         sL[BM];

    int tid  = threadIdx.x;
    int lane = tid & 31;
    int w    = tid >> 5;          // 0..3
    int pair = w >> 1;            // key-tile parity this warp handles
    int wp   = w & 1;             // warp-in-pair: row half
    int pt   = tid & 63;          // pair-local thread id
    int gid  = lane >> 2;
    int tg   = lane & 3;
    int b    = blockIdx.x / QT;
    int qt   = blockIdx.x % QT;
    long qbase = (long)b * NN + (long)qt * BM;
    long kb0   = (long)b * NN;

    float gmm = gamma_p[0];

    // Ones B-fragment for rowsum MMA: column n=0 of B[k,n] = 1.0 (bf16).
    uint32_t one2 = (lane < 4) ? 0x3F803F80u : 0u;
    uint32_t bones[2] = { one2, one2 };

    // Prologue: G tile + each pair's first key tile (kt = pair).
    if (tid < 64) cp_async16(&sG[tid * 8], &g_g[(qbase + tid) * QD]);
    {
        long kb = kb0 + (long)pair * BN;
        cp_async16(&sF[pair][0][pt * 8], &g_f[(kb + pt) * QD]);
#pragma unroll
        for (int i = 0; i < 8; i++) {
            int idx = pt + 64 * i;
            cp_async16(&sH[pair][0][(idx >> 3) * LDH + (idx & 7) * 8],
                       &g_h[kb * CC + idx * 8]);
        }
    }
    cp_async_commit();
    cp_async_wait0();
    __syncthreads();

    // G A-fragments for rows wp*32 + {gid, gid+8, gid+16, gid+24}.
    uint32_t ga0[2], ga1[2];
    ga0[0] = *(const uint32_t*)&sG[(wp * 32 + gid)      * QD + 2 * tg];
    ga0[1] = *(const uint32_t*)&sG[(wp * 32 + gid + 8)  * QD + 2 * tg];
    ga1[0] = *(const uint32_t*)&sG[(wp * 32 + gid + 16) * QD + 2 * tg];
    ga1[1] = *(const uint32_t*)&sG[(wp * 32 + gid + 24) * QD + 2 * tg];

    float o0[8][4], o1[8][4];
#pragma unroll
    for (int n = 0; n < 8; n++)
#pragma unroll
        for (int i = 0; i < 4; i++) { o0[n][i] = 0.f; o1[n][i] = 0.f; }
    float lacc0[4] = {0.f, 0.f, 0.f, 0.f};
    float lacc1[4] = {0.f, 0.f, 0.f, 0.f};

    // F-fragment smem offset for slab j: row j*8+gid, cols 2tg.
    int foff = gid * QD + 2 * tg;

    // Pipeline prologue: issue S for slab 0 of the first tile.
    float sA00[4], sA01[4], sA10[4], sA11[4];
#pragma unroll
    for (int v = 0; v < 4; v++) { sA00[v] = sA01[v] = sA10[v] = sA11[v] = 0.f; }
    {
        uint32_t f0 = *(const uint32_t*)&sF[pair][0][foff];
        uint32_t f1 = *(const uint32_t*)&sF[pair][0][8 * QD + foff];
        mma_16n8k8(sA00, ga0, f0);
        mma_16n8k8(sA01, ga0, f1);
        mma_16n8k8(sA10, ga1, f0);
        mma_16n8k8(sA11, ga1, f1);
    }

    const int NI = KT / 2;   // 32 iterations per pair
    for (int i = 0; i < NI; i++) {
        int buf = i & 1;
        const __nv_bfloat16* hb = &sH[pair][buf][0];
        const __nv_bfloat16* fbuf = &sF[pair][buf][0];

        // Prefetch this pair's next key tile (kt = 2*(i+1)+pair).
        if (i + 1 < NI) {
            long kb = kb0 + (long)(2 * (i + 1) + pair) * BN;
            cp_async16(&sF[pair][buf ^ 1][pt * 8], &g_f[(kb + pt) * QD]);
#pragma unroll
            for (int j = 0; j < 8; j++) {
                int idx = pt + 64 * j;
                cp_async16(&sH[pair][buf ^ 1][(idx >> 3) * LDH + (idx & 7) * 8],
                           &g_h[kb * CC + idx * 8]);
            }
            cp_async_commit();
        }

        // Modulo-scheduled slabs: S(kk+1) issued before ex2/PV of slab kk.
#pragma unroll
        for (int kk = 0; kk < 4; kk++) {
            float sB00[4], sB01[4], sB10[4], sB11[4];
            if (kk < 3) {
                uint32_t f0 = *(const uint32_t*)&fbuf[(2 * kk + 2) * 8 * QD + foff];
                uint32_t f1 = *(const uint32_t*)&fbuf[(2 * kk + 3) * 8 * QD + foff];
#pragma unroll
                for (int v = 0; v < 4; v++)
                    { sB00[v] = sB01[v] = sB10[v] = sB11[v] = 0.f; }
                mma_16n8k8(sB00, ga0, f0);
                mma_16n8k8(sB01, ga0, f1);
                mma_16n8k8(sB10, ga1, f0);
                mma_16n8k8(sB11, ga1, f1);
            }

            uint32_t a0[4], a1[4];
            a0[0] = ex2_pair(sA00[0], sA00[1]);
            a0[1] = ex2_pair(sA00[2], sA00[3]);
            a0[2] = ex2_pair(sA01[0], sA01[1]);
            a0[3] = ex2_pair(sA01[2], sA01[3]);
            a1[0] = ex2_pair(sA10[0], sA10[1]);
            a1[1] = ex2_pair(sA10[2], sA10[3]);
            a1[2] = ex2_pair(sA11[0], sA11[1]);
            a1[3] = ex2_pair(sA11[2], sA11[3]);

            // Row-sums on the tensor pipe (exact sum of the rounded P).
            mma_16n8k16(lacc0, a0, bones);
            mma_16n8k16(lacc1, a1, bones);

#pragma unroll
            for (int np = 0; np < 4; np++) {
                uint32_t bfr[4];
                ldsm_x4_trans(bfr,
                    &hb[(kk * 16 + (lane & 15)) * LDH + np * 16 + (lane >> 4) * 8]);
                mma_16n8k16(o0[2 * np],     a0, &bfr[0]);
                mma_16n8k16(o0[2 * np + 1], a0, &bfr[2]);
                mma_16n8k16(o1[2 * np],     a1, &bfr[0]);
                mma_16n8k16(o1[2 * np + 1], a1, &bfr[2]);
            }

            if (kk < 3) {
#pragma unroll
                for (int v = 0; v < 4; v++) {
                    sA00[v] = sB00[v]; sA01[v] = sB01[v];
                    sA10[v] = sB10[v]; sA11[v] = sB11[v];
                }
            }
        }

        if (i + 1 < NI) {
            cp_async_wait0();
            asm volatile("bar.sync %0, 64;\n" :: "r"(1 + pair) : "memory");

            // Cross-iteration pipeline: issue S for slab 0 of the NEXT tile
            // now; its latency hides under the barrier exit + prefetch issue.
            const __nv_bfloat16* fnext = &sF[pair][buf ^ 1][0];
            uint32_t f0 = *(const uint32_t*)&fnext[foff];
            uint32_t f1 = *(const uint32_t*)&fnext[8 * QD + foff];
#pragma unroll
            for (int v = 0; v < 4; v++)
                { sA00[v] = sA01[v] = sA10[v] = sA11[v] = 0.f; }
            mma_16n8k8(sA00, ga0, f0);
            mma_16n8k8(sA01, ga0, f1);
            mma_16n8k8(sA10, ga1, f0);
            mma_16n8k8(sA11, ga1, f1);
        }
    }

    // Row-sums live in column 0 of lacc (lanes with tg==0). Broadcast to the
    // 4 lanes of each row group.
    int src = lane & 28;
    float l0 = __shfl_sync(0xffffffffu, lacc0[0], src);
    float l1 = __shfl_sync(0xffffffffu, lacc0[2], src);
    float l2 = __shfl_sync(0xffffffffu, lacc1[0], src);
    float l3 = __shfl_sync(0xffffffffu, lacc1[2], src);

    // Symmetric epilogue: pair finalizes its rows [pair*32, pair*32+32); the
    // warp whose rows belong to the OTHER pair parks partials in smem.
    __syncthreads();
    float* sO = (float*)&sH[0][0][0];   // 64 x LDO floats (< 36 KB)
    int r0 = wp * 32 + gid;
    if (pair != wp) {
#pragma unroll
        for (int n = 0; n < 8; n++) {
            int col = n * 8 + 2 * tg;
            *(float2*)&sO[(r0)      * LDO + col] = make_float2(o0[n][0], o0[n][1]);
            *(float2*)&sO[(r0 + 8)  * LDO + col] = make_float2(o0[n][2], o0[n][3]);
            *(float2*)&sO[(r0 + 16) * LDO + col] = make_float2(o1[n][0], o1[n][1]);
            *(float2*)&sO[(r0 + 24) * LDO + col] = make_float2(o1[n][2], o1[n][3]);
        }
        if (tg == 0) {
            sL[r0] = l0; sL[r0 + 8] = l1; sL[r0 + 16] = l2; sL[r0 + 24] = l3;
        }
    }
    __syncthreads();
    if (pair == wp) {
        float inv0 = gmm / (l0 + sL[r0]);
        float inv1 = gmm / (l1 + sL[r0 + 8]);
        float inv2 = gmm / (l2 + sL[r0 + 16]);
        float inv3 = gmm / (l3 + sL[r0 + 24]);
        long rg = qbase + r0;
#pragma unroll
        for (int n = 0; n < 8; n++) {
            int col = n * 8 + 2 * tg;
            float2 p0 = *(const float2*)&sO[(r0)      * LDO + col];
            float2 p1 = *(const float2*)&sO[(r0 + 8)  * LDO + col];
            float2 p2 = *(const float2*)&sO[(r0 + 16) * LDO + col];
            float2 p3 = *(const float2*)&sO[(r0 + 24) * LDO + col];
            float2 x0 = *(const float2*)&x[(rg)      * CC + col];
            float2 x1 = *(const float2*)&x[(rg + 8)  * CC + col];
            float2 x2 = *(const float2*)&x[(rg + 16) * CC + col];
            float2 x3 = *(const float2*)&x[(rg + 24) * CC + col];
            float2 v;
            v.x = (o0[n][0] + p0.x) * inv0 + x0.x;
            v.y = (o0[n][1] + p0.y) * inv0 + x0.y;
            *(float2*)&out[(rg)      * CC + col] = v;
            v.x = (o0[n][2] + p1.x) * inv1 + x1.x;
            v.y = (o0[n][3] + p1.y) * inv1 + x1.y;
            *(float2*)&out[(rg + 8)  * CC + col] = v;
            v.x = (o1[n][0] + p2.x) * inv2 + x2.x;
            v.y = (o1[n][1] + p2.y) * inv2 + x2.y;
            *(float2*)&out[(rg + 16) * CC + col] = v;
            v.x = (o1[n][2] + p3.x) * inv3 + x3.x;
            v.y = (o1[n][3] + p3.y) * inv3 + x3.y;
            *(float2*)&out[(rg + 24) * CC + col] = v;
        }
    }
}

// ---------------------------------------------------------------------------

extern "C" void kernel_launch(void* const* d_in, const int* in_sizes, int n_in,
                              void* d_out, int out_size)
{
    const float* x     = (const float*)d_in[0];
    const float* kf    = (const float*)d_in[1];
    const float* kg    = (const float*)d_in[2];
    const float* kh    = (const float*)d_in[3];
    const float* gamma = (const float*)d_in[4];
    float*       out   = (float*)d_out;

    proj_kernel<<<(BB * NN) / 64, 128>>>(x, kf, kg, kh);
    attn_kernel<<<BB * QT, 128>>>(x, gamma, out);
}

// round 17
// speedup vs baseline: 1.0495x; 1.0495x over previous
#include <cuda_runtime.h>
#include <cuda_bf16.h>
#include <stdint.h>

#define BB 8
#define NN 4096
#define CC 64
#define QD 8
#define BM 64          // query rows per block
#define BN 64          // key tile rows
#define QT (NN / BM)
#define KT (NN / BN)
#define LDH 72         // sH leading dim
#define LDO 72         // epilogue O overlay leading dim (floats)
#define LOG2E 1.4426950408889634f

// Static device scratch for projections.
__device__ __nv_bfloat16 g_f[BB * NN * QD];   // 0.5 MB
__device__ __nv_bfloat16 g_g[BB * NN * QD];   // 0.5 MB (pre-scaled by log2e)
__device__ __nv_bfloat16 g_h[BB * NN * CC];   // 4 MB

// ---------------------------------------------------------------------------
// PTX helpers
// ---------------------------------------------------------------------------
__device__ __forceinline__ void mma_16n8k8(float* c, const uint32_t* a, uint32_t b)
{
    asm volatile(
        "mma.sync.aligned.m16n8k8.row.col.f32.bf16.bf16.f32 "
        "{%0,%1,%2,%3}, {%4,%5}, {%6}, {%0,%1,%2,%3};\n"
        : "+f"(c[0]), "+f"(c[1]), "+f"(c[2]), "+f"(c[3])
        : "r"(a[0]), "r"(a[1]), "r"(b));
}

__device__ __forceinline__ void mma_16n8k16(float* c, const uint32_t* a, const uint32_t* b)
{
    asm volatile(
        "mma.sync.aligned.m16n8k16.row.col.f32.bf16.bf16.f32 "
        "{%0,%1,%2,%3}, {%4,%5,%6,%7}, {%8,%9}, {%0,%1,%2,%3};\n"
        : "+f"(c[0]), "+f"(c[1]), "+f"(c[2]), "+f"(c[3])
        : "r"(a[0]), "r"(a[1]), "r"(a[2]), "r"(a[3]), "r"(b[0]), "r"(b[1]));
}

__device__ __forceinline__ void ldsm_x4(uint32_t* r, const void* smem_ptr)
{
    uint32_t addr = (uint32_t)__cvta_generic_to_shared(smem_ptr);
    asm volatile(
        "ldmatrix.sync.aligned.m8n8.x4.shared.b16 {%0,%1,%2,%3}, [%4];\n"
        : "=r"(r[0]), "=r"(r[1]), "=r"(r[2]), "=r"(r[3]) : "r"(addr));
}

__device__ __forceinline__ void ldsm_x4_trans(uint32_t* r, const void* smem_ptr)
{
    uint32_t addr = (uint32_t)__cvta_generic_to_shared(smem_ptr);
    asm volatile(
        "ldmatrix.sync.aligned.m8n8.x4.trans.shared.b16 {%0,%1,%2,%3}, [%4];\n"
        : "=r"(r[0]), "=r"(r[1]), "=r"(r[2]), "=r"(r[3]) : "r"(addr));
}

__device__ __forceinline__ uint32_t pack_bf162(float a, float b)
{
    __nv_bfloat162 t = __floats2bfloat162_rn(a, b);
    return *(uint32_t*)&t;
}

// cvt two fp32 -> bf16x2 (lo, hi), then exp2 both halves in ONE MUFU op.
__device__ __forceinline__ uint32_t ex2_pair(float lo, float hi)
{
    uint32_t t, y;
    asm("cvt.rn.bf16x2.f32 %0, %1, %2;\n" : "=r"(t) : "f"(hi), "f"(lo));
    asm("ex2.approx.ftz.bf16x2 %0, %1;\n" : "=r"(y) : "r"(t));
    return y;
}

__device__ __forceinline__ void cp_async16(void* smem_dst, const void* gmem_src)
{
    uint32_t d = (uint32_t)__cvta_generic_to_shared(smem_dst);
    asm volatile("cp.async.cg.shared.global [%0], [%1], 16;\n"
                 :: "r"(d), "l"(gmem_src) : "memory");
}
__device__ __forceinline__ void cp_async_commit()
{
    asm volatile("cp.async.commit_group;\n" ::: "memory");
}
__device__ __forceinline__ void cp_async_wait0()
{
    asm volatile("cp.async.wait_group 0;\n" ::: "memory");
}

// ---------------------------------------------------------------------------
// Kernel 1: projections as HMMA GEMM.  [64 rows x 64] @ [64 x 80] per block.
// 512 blocks x 128 threads (4 warps, 16 rows each), float4 weight staging.
// Wg pre-scaled by log2e.
// ---------------------------------------------------------------------------
#define LDW 88
#define LDX 72
__global__ __launch_bounds__(128) void proj_kernel(
    const float* __restrict__ x,
    const float* __restrict__ kf,
    const float* __restrict__ kg,
    const float* __restrict__ kh)
{
    __shared__ __nv_bfloat16 sW[64 * LDW];    // row c: d 0-7 f, 8-15 g(scaled), 16-79 h
    __shared__ __nv_bfloat16 sX[64 * LDX];

    int tid  = threadIdx.x;
    int lane = tid & 31;
    int w    = tid >> 5;
    int gid  = lane >> 2;
    int tg   = lane & 3;

    // Vectorized weight staging: flat float4 index over [kf | kg | kh].
    for (int i = tid; i < 1280; i += 128) {
        float4 v;
        int c, d;
        float sc = 1.f;
        if (i < 128) {
            v = ((const float4*)kf)[i];
            int e = i * 4;  c = e >> 3;  d = e & 7;
        } else if (i < 256) {
            v = ((const float4*)kg)[i - 128];
            int e = (i - 128) * 4;  c = e >> 3;  d = (e & 7) + 8;
            sc = LOG2E;
        } else {
            v = ((const float4*)kh)[i - 256];
            int e = (i - 256) * 4;  c = e >> 6;  d = (e & 63) + 16;
        }
        __nv_bfloat16* dst = &sW[c * LDW + d];
        dst[0] = __float2bfloat16(v.x * sc);
        dst[1] = __float2bfloat16(v.y * sc);
        dst[2] = __float2bfloat16(v.z * sc);
        dst[3] = __float2bfloat16(v.w * sc);
    }
    long base = (long)blockIdx.x * 64;
    const float4* xg = (const float4*)(x + base * 64);
    for (int i = tid; i < 1024; i += 128) {
        int r = i >> 4, c4 = (i & 15) * 4;
        float4 v = xg[i];
        __nv_bfloat162* dst = (__nv_bfloat162*)&sX[r * LDX + c4];
        dst[0] = __floats2bfloat162_rn(v.x, v.y);
        dst[1] = __floats2bfloat162_rn(v.z, v.w);
    }
    __syncthreads();

    float c[10][4];
#pragma unroll
    for (int n = 0; n < 10; n++)
#pragma unroll
        for (int i = 0; i < 4; i++) c[n][i] = 0.f;

#pragma unroll
    for (int kk = 0; kk < 4; kk++) {
        uint32_t a[4];
        ldsm_x4(a, &sX[(w * 16 + (lane & 15)) * LDX + kk * 16 + (lane >> 4) * 8]);
#pragma unroll
        for (int np = 0; np < 5; np++) {
            uint32_t bfr[4];
            ldsm_x4_trans(bfr,
                &sW[(kk * 16 + (lane & 15)) * LDW + np * 16 + (lane >> 4) * 8]);
            mma_16n8k16(c[2 * np],     a, &bfr[0]);
            mma_16n8k16(c[2 * np + 1], a, &bfr[2]);
        }
    }

    // Fragment-direct scattered stores: d = 16*np + 8*h + 2*tg (static routing).
    long r0 = base + w * 16 + gid;
    long r1 = r0 + 8;
#pragma unroll
    for (int np = 0; np < 5; np++) {
#pragma unroll
        for (int h = 0; h < 2; h++) {
            int dbase = 16 * np + 8 * h;
            uint32_t u0 = pack_bf162(c[2 * np + h][0], c[2 * np + h][1]);
            uint32_t u1 = pack_bf162(c[2 * np + h][2], c[2 * np + h][3]);
            if (dbase == 0) {
                *(uint32_t*)&g_f[r0 * QD + 2 * tg] = u0;
                *(uint32_t*)&g_f[r1 * QD + 2 * tg] = u1;
            } else if (dbase == 8) {
                *(uint32_t*)&g_g[r0 * QD + 2 * tg] = u0;
                *(uint32_t*)&g_g[r1 * QD + 2 * tg] = u1;
            } else {
                int d = dbase - 16 + 2 * tg;
                *(uint32_t*)&g_h[r0 * CC + d] = u0;
                *(uint32_t*)&g_h[r1 * CC + d] = u1;
            }
        }
    }
}

// ---------------------------------------------------------------------------
// Kernel 2: flash attention. 128 threads = 2 key-parity pairs (2 warps each).
// Pair p handles key tiles kt = p, p+2, ...; warp-in-pair wp covers rows
// [wp*32, wp*32+32) as two m16 chunks sharing every H B-fragment.
// S software-pipelined one slab ahead WITHIN the tile via parity ping-pong
// buffers (no copy chains); F fragments loaded per-slab (2 LDS.32) one slab
// ahead. Row-sums on the tensor pipe (ones column). Symmetric epilogue.
// Reg budget capped at 128 (4 blocks/SM residency).
// ---------------------------------------------------------------------------
__global__ __launch_bounds__(128, 4) void attn_kernel(
    const float* __restrict__ x,
    const float* __restrict__ gamma_p,
    float* __restrict__ out)
{
    __shared__ __nv_bfloat16 sG[BM * QD];             // 1 KB
    __shared__ __nv_bfloat16 sF[2][2][BN * QD];       // 4 KB   [pair][buf]
    __shared__ __nv_bfloat16 sH[2][2][BN * LDH];      // 36 KB  [pair][buf]
    __shared__ float         sL[BM];

    int tid  = threadIdx.x;
    int lane = tid & 31;
    int w    = tid >> 5;          // 0..3
    int pair = w >> 1;            // key-tile parity this warp handles
    int wp   = w & 1;             // warp-in-pair: row half
    int pt   = tid & 63;          // pair-local thread id
    int gid  = lane >> 2;
    int tg   = lane & 3;
    int b    = blockIdx.x / QT;
    int qt   = blockIdx.x % QT;
    long qbase = (long)b * NN + (long)qt * BM;
    long kb0   = (long)b * NN;

    float gmm = gamma_p[0];

    // Ones B-fragment for rowsum MMA: column n=0 of B[k,n] = 1.0 (bf16).
    uint32_t one2 = (lane < 4) ? 0x3F803F80u : 0u;
    uint32_t bones[2] = { one2, one2 };

    // Prologue: G tile + each pair's first key tile (kt = pair).
    if (tid < 64) cp_async16(&sG[tid * 8], &g_g[(qbase + tid) * QD]);
    {
        long kb = kb0 + (long)pair * BN;
        cp_async16(&sF[pair][0][pt * 8], &g_f[(kb + pt) * QD]);
#pragma unroll
        for (int i = 0; i < 8; i++) {
            int idx = pt + 64 * i;
            cp_async16(&sH[pair][0][(idx >> 3) * LDH + (idx & 7) * 8],
                       &g_h[kb * CC + idx * 8]);
        }
    }
    cp_async_commit();
    cp_async_wait0();
    __syncthreads();

    // G A-fragments for rows wp*32 + {gid, gid+8, gid+16, gid+24}.
    uint32_t ga0[2], ga1[2];
    ga0[0] = *(const uint32_t*)&sG[(wp * 32 + gid)      * QD + 2 * tg];
    ga0[1] = *(const uint32_t*)&sG[(wp * 32 + gid + 8)  * QD + 2 * tg];
    ga1[0] = *(const uint32_t*)&sG[(wp * 32 + gid + 16) * QD + 2 * tg];
    ga1[1] = *(const uint32_t*)&sG[(wp * 32 + gid + 24) * QD + 2 * tg];

    float o0[8][4], o1[8][4];
#pragma unroll
    for (int n = 0; n < 8; n++)
#pragma unroll
        for (int i = 0; i < 4; i++) { o0[n][i] = 0.f; o1[n][i] = 0.f; }
    float lacc0[4] = {0.f, 0.f, 0.f, 0.f};
    float lacc1[4] = {0.f, 0.f, 0.f, 0.f};

    // F-fragment smem offset for slab j: row j*8+gid, col 2tg.
    int foff = gid * QD + 2 * tg;

    const int NI = KT / 2;   // 32 iterations per pair
    for (int i = 0; i < NI; i++) {
        int buf = i & 1;
        const __nv_bfloat16* hb   = &sH[pair][buf][0];
        const __nv_bfloat16* fbuf = &sF[pair][buf][0];

        // Prefetch this pair's next key tile (kt = 2*(i+1)+pair).
        if (i + 1 < NI) {
            long kb = kb0 + (long)(2 * (i + 1) + pair) * BN;
            cp_async16(&sF[pair][buf ^ 1][pt * 8], &g_f[(kb + pt) * QD]);
#pragma unroll
            for (int j = 0; j < 8; j++) {
                int idx = pt + 64 * j;
                cp_async16(&sH[pair][buf ^ 1][(idx >> 3) * LDH + (idx & 7) * 8],
                           &g_h[kb * CC + idx * 8]);
            }
            cp_async_commit();
        }

        // Ping-pong S buffers indexed by slab parity (constant after unroll).
        float sS[2][4][4];   // [parity][frag 00,01,10,11][4]

        // Pipeline prologue: S for slab 0 into parity 0.
        {
            uint32_t f0 = *(const uint32_t*)&fbuf[foff];
            uint32_t f1 = *(const uint32_t*)&fbuf[8 * QD + foff];
#pragma unroll
            for (int q = 0; q < 4; q++)
#pragma unroll
                for (int v = 0; v < 4; v++) sS[0][q][v] = 0.f;
            mma_16n8k8(sS[0][0], ga0, f0);
            mma_16n8k8(sS[0][1], ga0, f1);
            mma_16n8k8(sS[0][2], ga1, f0);
            mma_16n8k8(sS[0][3], ga1, f1);
        }

#pragma unroll
        for (int kk = 0; kk < 4; kk++) {
            const int cur = kk & 1;
            const int nxt = cur ^ 1;

            // Issue S for slab kk+1 into the other parity buffer.
            if (kk < 3) {
                uint32_t f0 = *(const uint32_t*)&fbuf[(2 * kk + 2) * 8 * QD + foff];
                uint32_t f1 = *(const uint32_t*)&fbuf[(2 * kk + 3) * 8 * QD + foff];
#pragma unroll
                for (int q = 0; q < 4; q++)
#pragma unroll
                    for (int v = 0; v < 4; v++) sS[nxt][q][v] = 0.f;
                mma_16n8k8(sS[nxt][0], ga0, f0);
                mma_16n8k8(sS[nxt][1], ga0, f1);
                mma_16n8k8(sS[nxt][2], ga1, f0);
                mma_16n8k8(sS[nxt][3], ga1, f1);
            }

            uint32_t a0[4], a1[4];
            a0[0] = ex2_pair(sS[cur][0][0], sS[cur][0][1]);
            a0[1] = ex2_pair(sS[cur][0][2], sS[cur][0][3]);
            a0[2] = ex2_pair(sS[cur][1][0], sS[cur][1][1]);
            a0[3] = ex2_pair(sS[cur][1][2], sS[cur][1][3]);
            a1[0] = ex2_pair(sS[cur][2][0], sS[cur][2][1]);
            a1[1] = ex2_pair(sS[cur][2][2], sS[cur][2][3]);
            a1[2] = ex2_pair(sS[cur][3][0], sS[cur][3][1]);
            a1[3] = ex2_pair(sS[cur][3][2], sS[cur][3][3]);

            // Row-sums on the tensor pipe (exact sum of the rounded P).
            mma_16n8k16(lacc0, a0, bones);
            mma_16n8k16(lacc1, a1, bones);

#pragma unroll
            for (int np = 0; np < 4; np++) {
                uint32_t bfr[4];
                ldsm_x4_trans(bfr,
                    &hb[(kk * 16 + (lane & 15)) * LDH + np * 16 + (lane >> 4) * 8]);
                mma_16n8k16(o0[2 * np],     a0, &bfr[0]);
                mma_16n8k16(o0[2 * np + 1], a0, &bfr[2]);
                mma_16n8k16(o1[2 * np],     a1, &bfr[0]);
                mma_16n8k16(o1[2 * np + 1], a1, &bfr[2]);
            }
        }

        if (i + 1 < NI) {
            cp_async_wait0();
            asm volatile("bar.sync %0, 64;\n" :: "r"(1 + pair) : "memory");
        }
    }

    // Row-sums live in column 0 of lacc (lanes with tg==0). Broadcast to the
    // 4 lanes of each row group.
    int src = lane & 28;
    float l0 = __shfl_sync(0xffffffffu, lacc0[0], src);
    float l1 = __shfl_sync(0xffffffffu, lacc0[2], src);
    float l2 = __shfl_sync(0xffffffffu, lacc1[0], src);
    float l3 = __shfl_sync(0xffffffffu, lacc1[2], src);

    // Symmetric epilogue: pair finalizes its rows [pair*32, pair*32+32); the
    // warp whose rows belong to the OTHER pair parks partials in smem.
    __syncthreads();
    float* sO = (float*)&sH[0][0][0];   // 64 x LDO floats (< 36 KB)
    int r0 = wp * 32 + gid;
    if (pair != wp) {
#pragma unroll
        for (int n = 0; n < 8; n++) {
            int col = n * 8 + 2 * tg;
            *(float2*)&sO[(r0)      * LDO + col] = make_float2(o0[n][0], o0[n][1]);
            *(float2*)&sO[(r0 + 8)  * LDO + col] = make_float2(o0[n][2], o0[n][3]);
            *(float2*)&sO[(r0 + 16) * LDO + col] = make_float2(o1[n][0], o1[n][1]);
            *(float2*)&sO[(r0 + 24) * LDO + col] = make_float2(o1[n][2], o1[n][3]);
        }
        if (tg == 0) {
            sL[r0] = l0; sL[r0 + 8] = l1; sL[r0 + 16] = l2; sL[r0 + 24] = l3;
        }
    }
    __syncthreads();
    if (pair == wp) {
        float inv0 = gmm / (l0 + sL[r0]);
        float inv1 = gmm / (l1 + sL[r0 + 8]);
        float inv2 = gmm / (l2 + sL[r0 + 16]);
        float inv3 = gmm / (l3 + sL[r0 + 24]);
        long rg = qbase + r0;
#pragma unroll
        for (int n = 0; n < 8; n++) {
            int col = n * 8 + 2 * tg;
            float2 p0 = *(const float2*)&sO[(r0)      * LDO + col];
            float2 p1 = *(const float2*)&sO[(r0 + 8)  * LDO + col];
            float2 p2 = *(const float2*)&sO[(r0 + 16) * LDO + col];
            float2 p3 = *(const float2*)&sO[(r0 + 24) * LDO + col];
            float2 x0 = *(const float2*)&x[(rg)      * CC + col];
            float2 x1 = *(const float2*)&x[(rg + 8)  * CC + col];
            float2 x2 = *(const float2*)&x[(rg + 16) * CC + col];
            float2 x3 = *(const float2*)&x[(rg + 24) * CC + col];
            float2 v;
            v.x = (o0[n][0] + p0.x) * inv0 + x0.x;
            v.y = (o0[n][1] + p0.y) * inv0 + x0.y;
            *(float2*)&out[(rg)      * CC + col] = v;
            v.x = (o0[n][2] + p1.x) * inv1 + x1.x;
            v.y = (o0[n][3] + p1.y) * inv1 + x1.y;
            *(float2*)&out[(rg + 8)  * CC + col] = v;
            v.x = (o1[n][0] + p2.x) * inv2 + x2.x;
            v.y = (o1[n][1] + p2.y) * inv2 + x2.y;
            *(float2*)&out[(rg + 16) * CC + col] = v;
            v.x = (o1[n][2] + p3.x) * inv3 + x3.x;
            v.y = (o1[n][3] + p3.y) * inv3 + x3.y;
            *(float2*)&out[(rg + 24) * CC + col] = v;
        }
    }
}

// ---------------------------------------------------------------------------

extern "C" void kernel_launch(void* const* d_in, const int* in_sizes, int n_in,
                              void* d_out, int out_size)
{
    const float* x     = (const float*)d_in[0];
    const float* kf    = (const float*)d_in[1];
    const float* kg    = (const float*)d_in[2];
    const float* kh    = (const float*)d_in[3];
    const float* gamma = (const float*)d_in[4];
    float*       out   = (float*)d_out;

    proj_kernel<<<(BB * NN) / 64, 128>>>(x, kf, kg, kh);
    attn_kernel<<<BB * QT, 128>>>(x, gamma, out);
}